// round 10
// baseline (speedup 1.0000x reference)
#include <cuda_runtime.h>
#include <cuda_bf16.h>
#include <cstdint>

#define S_DIM 16
#define P_DIM 65536
#define N_DIM 256
#define K_DIM 32
#define CH_FLOATS ((size_t)N_DIM * P_DIM)   // 16777216 floats per channel

// ---------------------------------------------------------------------------
// Branch B: fused fill+scatter for CHANNEL 0 only (64 MiB).
// Warp-granular: each warp owns 2048 floats of one row, zeroes them, then
// scatters the hot entries of that row landing in its range (c=0 values).
// grid = 256 rows * 4 segs = 1024 CTAs.
// ---------------------------------------------------------------------------
#define WARP_FLOATS 2048
#define CTA_FLOATS  (WARP_FLOATS * 8)       // 16384
#define VEC_PER_LANE (WARP_FLOATS / 4 / 32) // 16

__global__ void __launch_bounds__(256)
fused_ch0_kernel(const float4* __restrict__ schema_params, // [S, P] float4
                 const int* __restrict__ schema_ids,       // [N]
                 const int* __restrict__ indices,          // [N, K]
                 float* __restrict__ out)                  // [3, N, P]
{
    const int bid  = blockIdx.x;
    const int seg  = bid & 3;
    const int n    = bid >> 2;          // 0..255
    const int warp = threadIdx.x >> 5;
    const int lane = threadIdx.x & 31;

    const int range_lo = seg * CTA_FLOATS + warp * WARP_FLOATS;

    // Prefetch this lane's index; latency hides under the fill stores.
    const int p = __ldg(&indices[n * K_DIM + lane]);

    // ---- zero fill this warp's 2048 floats of channel 0 ----
    float4* wout = (float4*)(out + (size_t)n * P_DIM + range_lo);
    const float4 z = make_float4(0.f, 0.f, 0.f, 0.f);
#pragma unroll
    for (int j = 0; j < VEC_PER_LANE; j++) {
        wout[lane + 32 * j] = z;
    }

    __syncwarp();

    // ---- scatter channel-0 hot entries landing in this warp's range ----
    const bool in_range = ((unsigned)(p - range_lo) < (unsigned)WARP_FLOATS);

    unsigned mask   = __match_any_sync(0xffffffffu, p);
    int      count  = __popc(mask);
    bool     leader = (lane == (__ffs(mask) - 1));

    if (leader && in_range) {
        const int sid = __ldg(&schema_ids[n]);
        float4 sp = __ldg(&schema_params[(size_t)sid * P_DIM + p]);
        float v = sp.z + sp.w;          // channel 0 projection: f2+f3
        float b = 1.0f - v;
        float r = b;
        for (int i = 1; i < count; i++) r *= b;
        out[(size_t)n * P_DIM + p] = 1.0f - r;
    }
}

// ---------------------------------------------------------------------------
// Post-join scatter for channels 1 and 2 (runs after the memset node).
// One warp per row; all lanes issue dependent loads immediately.
// ---------------------------------------------------------------------------
__global__ void __launch_bounds__(32)
scatter12_kernel(const float4* __restrict__ schema_params,
                 const int* __restrict__ schema_ids,
                 const int* __restrict__ indices,
                 float* __restrict__ out)
{
    const int n    = blockIdx.x;        // 0..255
    const int lane = threadIdx.x;

    const int p   = __ldg(&indices[n * K_DIM + lane]);
    const int sid = __ldg(&schema_ids[n]);
    const float4 sp = __ldg(&schema_params[(size_t)sid * P_DIM + p]);

    unsigned mask   = __match_any_sync(0xffffffffu, p);
    int      count  = __popc(mask);
    bool     leader = (lane == (__ffs(mask) - 1));

    if (leader) {
        float b1 = 1.0f - sp.y;         // channel 1: f1
        float b2 = 1.0f - sp.w;         // channel 2: f3
        float r1 = b1, r2 = b2;
        for (int i = 1; i < count; i++) { r1 *= b1; r2 *= b2; }

        const size_t base = (size_t)n * P_DIM + p;
        out[CH_FLOATS + base]     = 1.0f - r1;
        out[2 * CH_FLOATS + base] = 1.0f - r2;
    }
}

extern "C" void kernel_launch(void* const* d_in, const int* in_sizes, int n_in,
                              void* d_out, int out_size) {
    const float4* schema_params = (const float4*)d_in[0];   // (16, 65536, 4) fp32
    const int*    schema_ids    = (const int*)d_in[1];      // (256,)
    const int*    indices       = (const int*)d_in[2];      // (256, 32)
    float*        out           = (float*)d_out;            // (3, 256, 65536) fp32

    // One-time host-side resources (no device memory allocation).
    static cudaStream_t s2 = nullptr;
    static cudaEvent_t  eFork = nullptr, eJoin = nullptr;
    if (s2 == nullptr) {
        cudaStreamCreateWithFlags(&s2, cudaStreamNonBlocking);
        cudaEventCreateWithFlags(&eFork, cudaEventDisableTiming);
        cudaEventCreateWithFlags(&eJoin, cudaEventDisableTiming);
    }

    // Fork: branch A (s2) = memset node zeroing channels 1 & 2 (128 MiB).
    cudaEventRecord(eFork, 0);
    cudaStreamWaitEvent(s2, eFork, 0);
    cudaMemsetAsync(out + CH_FLOATS, 0, 2 * CH_FLOATS * sizeof(float), s2);

    // Branch B (origin stream) = SM fill+scatter of channel 0 (64 MiB).
    fused_ch0_kernel<<<N_DIM * 4, 256>>>(schema_params, schema_ids, indices, out);

    // Join, then scatter the channel-1/2 hot entries.
    cudaEventRecord(eJoin, s2);
    cudaStreamWaitEvent(0, eJoin, 0);
    scatter12_kernel<<<N_DIM, 32>>>(schema_params, schema_ids, indices, out);
}

// round 11
// speedup vs baseline: 1.1493x; 1.1493x over previous
#include <cuda_runtime.h>
#include <cuda_bf16.h>
#include <cstdint>

#define S_DIM 16
#define P_DIM 65536
#define N_DIM 256
#define K_DIM 32

// Warp-granular fused fill+scatter, fully hoisted scatter loads.
//
// All scatter inputs (indices, schema_ids, schema_params — all lanes) are
// loaded BEFORE the fill stores, so their latency hides entirely under the
// 16 STG.128s. The post-fill tail is just match + FMA + conditional STG
// (~30 cyc) instead of a dependent 234-600 cyc params load.
//
// Each warp owns a contiguous 2048-float range of one (channel,row).
// Cross-warp writes never alias -> __syncwarp() suffices.
// CTA = 8 warps = 16384 floats -> 4 CTAs per row; grid = 3*256*4 = 3072.
#define WARP_FLOATS 2048
#define CTA_FLOATS  (WARP_FLOATS * 8)       // 16384
#define VEC_PER_LANE (WARP_FLOATS / 4 / 32) // 16

__global__ void __launch_bounds__(256)
fused_kernel(const float4* __restrict__ schema_params, // [S, P] float4
             const int* __restrict__ schema_ids,       // [N]
             const int* __restrict__ indices,          // [N, K]
             float* __restrict__ out)                  // [3, N, P]
{
    const int bid  = blockIdx.x;
    const int seg  = bid & 3;           // which 16384-float chunk of the row
    const int row  = bid >> 2;          // 0..767
    const int c    = row >> 8;          // channel 0..2
    const int n    = row & 255;         // row 0..255
    const int warp = threadIdx.x >> 5;
    const int lane = threadIdx.x & 31;

    const int range_lo = seg * CTA_FLOATS + warp * WARP_FLOATS;

    // ---- Hoisted scatter loads: issue ALL dependent loads first (L2-hot,
    //      all lanes). Their latency hides under the fill stores below.
    const int p    = __ldg(&indices[n * K_DIM + lane]);
    const int sid  = __ldg(&schema_ids[n]);
    const float4 sp = __ldg(&schema_params[(size_t)sid * P_DIM + p]);

    // ---- Phase 1: zero fill this warp's 2048 floats (16 STG.128/lane) ----
    float4* wout = (float4*)(out + (size_t)row * P_DIM + range_lo);
    const float4 z = make_float4(0.f, 0.f, 0.f, 0.f);
#pragma unroll
    for (int j = 0; j < VEC_PER_LANE; j++) {
        wout[lane + 32 * j] = z;
    }

    __syncwarp();   // order this warp's zeros before its scatter write

    // ---- Phase 2: short tail — match + FMA + conditional STG ----
    const bool in_range = ((unsigned)(p - range_lo) < (unsigned)WARP_FLOATS);

    unsigned mask   = __match_any_sync(0xffffffffu, p);
    int      count  = __popc(mask);
    bool     leader = (lane == (__ffs(mask) - 1));

    if (leader && in_range) {
        // proj rows: c0 = f2+f3, c1 = f1, c2 = f3
        float v = (c == 0) ? (sp.z + sp.w) : (c == 1) ? sp.y : sp.w;
        float b = 1.0f - v;
        float r = b;
        for (int i = 1; i < count; i++) r *= b;
        out[(size_t)row * P_DIM + p] = 1.0f - r;
    }
}

extern "C" void kernel_launch(void* const* d_in, const int* in_sizes, int n_in,
                              void* d_out, int out_size) {
    const float4* schema_params = (const float4*)d_in[0];   // (16, 65536, 4) fp32
    const int*    schema_ids    = (const int*)d_in[1];      // (256,)
    const int*    indices       = (const int*)d_in[2];      // (256, 32)
    float*        out           = (float*)d_out;            // (3, 256, 65536) fp32

    const int blocks = 3 * N_DIM * (P_DIM / CTA_FLOATS);    // 3072
    fused_kernel<<<blocks, 256>>>(schema_params, schema_ids, indices, out);
}